// round 8
// baseline (speedup 1.0000x reference)
#include <cuda_runtime.h>
#include <cstdint>

// Submanifold 3x3 conv (cross-correlation, SAME) on independent 4x4x1 tiles.
// One thread handles TWO row-pair tasks (at gid and gid+half) for 2x MLP and
// amortized weight setup. Within a task: tile = 2 adjacent lanes, single
// butterfly exchange (shfl.xor 1) supplies the one partner row needed; both
// output rows computed together with packed fma.rn.f32x2.

__device__ __forceinline__ unsigned long long pk2(float lo, float hi) {
    unsigned long long r;
    asm("mov.b64 %0, {%1, %2};" : "=l"(r) : "f"(lo), "f"(hi));
    return r;
}
__device__ __forceinline__ unsigned long long fma2(
    unsigned long long a, unsigned long long b, unsigned long long c) {
    unsigned long long d;
    asm("fma.rn.f32x2 %0, %1, %2, %3;" : "=l"(d) : "l"(a), "l"(b), "l"(c));
    return d;
}
__device__ __forceinline__ unsigned long long mul2(
    unsigned long long a, unsigned long long b) {
    unsigned long long d;
    asm("mul.rn.f32x2 %0, %1, %2;" : "=l"(d) : "l"(a), "l"(b));
    return d;
}
__device__ __forceinline__ void upk2(unsigned long long v, float& lo, float& hi) {
    asm("mov.b64 {%0, %1}, %2;" : "=f"(lo), "=f"(hi) : "l"(v));
}

struct WW { unsigned long long w[9]; };

// Compute one row-pair task: rows (m, n) with exchanged row `recv`,
// top = (pair index even). Writes the two output float4s.
__device__ __forceinline__ void conv_pair(
    float4 m, float4 n, float4 recv, bool top, const WW& ww, float4* yout)
{
    float4 zero4 = make_float4(0.f, 0.f, 0.f, 0.f);
    float4 a = top ? zero4 : recv;   // row above m (zero at tile top)
    float4 b = top ? recv : zero4;   // row below n (zero at tile bottom)

    float ra[4] = {a.x, a.y, a.z, a.w};
    float rm[4] = {m.x, m.y, m.z, m.w};
    float rn[4] = {n.x, n.y, n.z, n.w};
    float rb[4] = {b.x, b.y, b.z, b.w};

    // lo half -> output row m (inputs ra,rm,rn); hi half -> row n (rm,rn,rb).
    unsigned long long P0[4], P1[4], P2[4];
#pragma unroll
    for (int c = 0; c < 4; c++) {
        P0[c] = pk2(ra[c], rm[c]);
        P1[c] = pk2(rm[c], rn[c]);
        P2[c] = pk2(rn[c], rb[c]);
    }

    unsigned long long S0, S1, S2, S3;
    // j = 0 (cols c=1,2 of the 3x3 window)
    S0 = mul2(P0[0], ww.w[1]);
    S0 = fma2(P1[0], ww.w[4], S0);
    S0 = fma2(P2[0], ww.w[7], S0);
    S0 = fma2(P0[1], ww.w[2], S0);
    S0 = fma2(P1[1], ww.w[5], S0);
    S0 = fma2(P2[1], ww.w[8], S0);
    // j = 1
    S1 = mul2(P0[0], ww.w[0]);
    S1 = fma2(P1[0], ww.w[3], S1);
    S1 = fma2(P2[0], ww.w[6], S1);
    S1 = fma2(P0[1], ww.w[1], S1);
    S1 = fma2(P1[1], ww.w[4], S1);
    S1 = fma2(P2[1], ww.w[7], S1);
    S1 = fma2(P0[2], ww.w[2], S1);
    S1 = fma2(P1[2], ww.w[5], S1);
    S1 = fma2(P2[2], ww.w[8], S1);
    // j = 2
    S2 = mul2(P0[1], ww.w[0]);
    S2 = fma2(P1[1], ww.w[3], S2);
    S2 = fma2(P2[1], ww.w[6], S2);
    S2 = fma2(P0[2], ww.w[1], S2);
    S2 = fma2(P1[2], ww.w[4], S2);
    S2 = fma2(P2[2], ww.w[7], S2);
    S2 = fma2(P0[3], ww.w[2], S2);
    S2 = fma2(P1[3], ww.w[5], S2);
    S2 = fma2(P2[3], ww.w[8], S2);
    // j = 3 (cols c=0,1)
    S3 = mul2(P0[2], ww.w[0]);
    S3 = fma2(P1[2], ww.w[3], S3);
    S3 = fma2(P2[2], ww.w[6], S3);
    S3 = fma2(P0[3], ww.w[1], S3);
    S3 = fma2(P1[3], ww.w[4], S3);
    S3 = fma2(P2[3], ww.w[7], S3);

    float o0[4], o1[4];
    upk2(S0, o0[0], o1[0]);
    upk2(S1, o0[1], o1[1]);
    upk2(S2, o0[2], o1[2]);
    upk2(S3, o0[3], o1[3]);

    // Submanifold mask: write only at active (nonzero-input) sites.
#pragma unroll
    for (int j = 0; j < 4; j++) {
        o0[j] = (rm[j] != 0.0f) ? o0[j] : 0.0f;
        o1[j] = (rn[j] != 0.0f) ? o1[j] : 0.0f;
    }

    __stcs(yout + 0, make_float4(o0[0], o0[1], o0[2], o0[3]));
    __stcs(yout + 1, make_float4(o1[0], o1[1], o1[2], o1[3]));
}

__global__ __launch_bounds__(256) void subm_conv_pair2_kernel(
    const float4* __restrict__ x,
    const float* __restrict__ W,
    float4* __restrict__ y,
    int n_half)
{
    int gid = blockIdx.x * blockDim.x + threadIdx.x;
    if (gid >= n_half) return;

    size_t i0 = (size_t)gid;
    size_t i1 = (size_t)gid + (size_t)n_half;   // n_half even -> same parity

    // Issue all 4 data loads up-front (streaming; max MLP).
    const float4* b0 = x + 2 * i0;
    const float4* b1 = x + 2 * i1;
    float4 m0 = __ldcs(b0 + 0);
    float4 n0 = __ldcs(b0 + 1);
    float4 m1 = __ldcs(b1 + 0);
    float4 n1 = __ldcs(b1 + 1);

    // Broadcast weight loads (uniform address -> L1 broadcast hits).
    float4 w03 = __ldg(reinterpret_cast<const float4*>(W));
    float4 w47 = __ldg(reinterpret_cast<const float4*>(W) + 1);
    float  w8f = __ldg(W + 8);

    bool top = ((gid & 1) == 0);  // both tasks share parity (n_half even)

    // Butterfly exchanges with partner lane (lane ^ 1), both tasks.
    float4 s0 = top ? n0 : m0;
    float4 s1 = top ? n1 : m1;
    float4 r0, r1;
    r0.x = __shfl_xor_sync(0xffffffffu, s0.x, 1);
    r0.y = __shfl_xor_sync(0xffffffffu, s0.y, 1);
    r0.z = __shfl_xor_sync(0xffffffffu, s0.z, 1);
    r0.w = __shfl_xor_sync(0xffffffffu, s0.w, 1);
    r1.x = __shfl_xor_sync(0xffffffffu, s1.x, 1);
    r1.y = __shfl_xor_sync(0xffffffffu, s1.y, 1);
    r1.z = __shfl_xor_sync(0xffffffffu, s1.z, 1);
    r1.w = __shfl_xor_sync(0xffffffffu, s1.w, 1);

    // Packed weights, shared by both tasks.
    WW ww;
    ww.w[0] = pk2(w03.x, w03.x);
    ww.w[1] = pk2(w03.y, w03.y);
    ww.w[2] = pk2(w03.z, w03.z);
    ww.w[3] = pk2(w03.w, w03.w);
    ww.w[4] = pk2(w47.x, w47.x);
    ww.w[5] = pk2(w47.y, w47.y);
    ww.w[6] = pk2(w47.z, w47.z);
    ww.w[7] = pk2(w47.w, w47.w);
    ww.w[8] = pk2(w8f,  w8f);

    conv_pair(m0, n0, r0, top, ww, y + 2 * i0);
    conv_pair(m1, n1, r1, top, ww, y + 2 * i1);
}

extern "C" void kernel_launch(void* const* d_in, const int* in_sizes, int n_in,
                              void* d_out, int out_size)
{
    const float4* x = (const float4*)d_in[0];
    const float* W = (const float*)d_in[1];
    float4* y = (float4*)d_out;

    int n_pairs = in_sizes[0] / 8;   // row-pairs (8 floats each)
    int n_half = n_pairs / 2;        // two tasks per thread
    int threads = 256;
    int blocks = (n_half + threads - 1) / threads;
    subm_conv_pair2_kernel<<<blocks, threads>>>(x, W, y, n_half);
}

// round 9
// speedup vs baseline: 1.0382x; 1.0382x over previous
#include <cuda_runtime.h>
#include <cstdint>

// Submanifold 3x3 conv (cross-correlation, SAME) on independent 4x4x1 tiles.
// One thread per ROW-PAIR (2x float4 = 32B); tile = 2 adjacent lanes.
// Single butterfly exchange (shfl.xor 1) supplies the one partner row each
// lane needs. Both output rows computed together with packed fma.rn.f32x2.
// Reads use __ldcs (evict-first: streaming reads self-evict, sparing L2);
// stores use DEFAULT evict-normal so dirty output lines linger in L2 and a
// chunk of the write stream never hits DRAM inside the timed window.

__device__ __forceinline__ unsigned long long pk2(float lo, float hi) {
    unsigned long long r;
    asm("mov.b64 %0, {%1, %2};" : "=l"(r) : "f"(lo), "f"(hi));
    return r;
}
__device__ __forceinline__ unsigned long long fma2(
    unsigned long long a, unsigned long long b, unsigned long long c) {
    unsigned long long d;
    asm("fma.rn.f32x2 %0, %1, %2, %3;" : "=l"(d) : "l"(a), "l"(b), "l"(c));
    return d;
}
__device__ __forceinline__ unsigned long long mul2(
    unsigned long long a, unsigned long long b) {
    unsigned long long d;
    asm("mul.rn.f32x2 %0, %1, %2;" : "=l"(d) : "l"(a), "l"(b));
    return d;
}
__device__ __forceinline__ void upk2(unsigned long long v, float& lo, float& hi) {
    asm("mov.b64 {%0, %1}, %2;" : "=f"(lo), "=f"(hi) : "l"(v));
}

__global__ __launch_bounds__(256) void subm_conv_pair_f32x2_kernel(
    const float4* __restrict__ x,
    const float* __restrict__ W,
    float4* __restrict__ y,
    int n_pairs)
{
    int gid = blockIdx.x * blockDim.x + threadIdx.x;
    if (gid >= n_pairs) return;

    const float4* xin = x + 2 * (size_t)gid;
    float4 r0 = __ldcs(xin + 0);
    float4 r1 = __ldcs(xin + 1);
    bool top = ((gid & 1) == 0);

    // Broadcast weight loads (uniform address -> L1 broadcast hits).
    float4 w03 = __ldg(reinterpret_cast<const float4*>(W));
    float4 w47 = __ldg(reinterpret_cast<const float4*>(W) + 1);
    float  w8f = __ldg(W + 8);

    // Butterfly exchange with partner lane (same tile).
    float4 send = top ? r1 : r0;
    float4 recv;
    recv.x = __shfl_xor_sync(0xffffffffu, send.x, 1);
    recv.y = __shfl_xor_sync(0xffffffffu, send.y, 1);
    recv.z = __shfl_xor_sync(0xffffffffu, send.z, 1);
    recv.w = __shfl_xor_sync(0xffffffffu, send.w, 1);

    float4 zero4 = make_float4(0.f, 0.f, 0.f, 0.f);
    float4 a = top ? zero4 : recv;   // row above r0 (zero at tile top)
    float4 b = top ? recv : zero4;   // row below r1 (zero at tile bottom)

    float ra[4] = {a.x,  a.y,  a.z,  a.w};
    float rm[4] = {r0.x, r0.y, r0.z, r0.w};
    float rn[4] = {r1.x, r1.y, r1.z, r1.w};
    float rb[4] = {b.x,  b.y,  b.z,  b.w};

    // Packed input rows: lo half -> output row r0 (inputs ra,rm,rn),
    // hi half -> output row r1 (inputs rm,rn,rb).
    unsigned long long P0[4], P1[4], P2[4];
#pragma unroll
    for (int c = 0; c < 4; c++) {
        P0[c] = pk2(ra[c], rm[c]);
        P1[c] = pk2(rm[c], rn[c]);
        P2[c] = pk2(rn[c], rb[c]);
    }

    unsigned long long ww[9];
    ww[0] = pk2(w03.x, w03.x);
    ww[1] = pk2(w03.y, w03.y);
    ww[2] = pk2(w03.z, w03.z);
    ww[3] = pk2(w03.w, w03.w);
    ww[4] = pk2(w47.x, w47.x);
    ww[5] = pk2(w47.y, w47.y);
    ww[6] = pk2(w47.z, w47.z);
    ww[7] = pk2(w47.w, w47.w);
    ww[8] = pk2(w8f,  w8f);

    // S[j] = sum over weight rows k, cols c of Pk[j+c-1]*w[k][c]; taps with
    // j+c-1 outside [0,3] are zero (dropped).
    unsigned long long S0, S1, S2, S3;
    // j = 0
    S0 = mul2(P0[0], ww[1]);
    S0 = fma2(P1[0], ww[4], S0);
    S0 = fma2(P2[0], ww[7], S0);
    S0 = fma2(P0[1], ww[2], S0);
    S0 = fma2(P1[1], ww[5], S0);
    S0 = fma2(P2[1], ww[8], S0);
    // j = 1
    S1 = mul2(P0[0], ww[0]);
    S1 = fma2(P1[0], ww[3], S1);
    S1 = fma2(P2[0], ww[6], S1);
    S1 = fma2(P0[1], ww[1], S1);
    S1 = fma2(P1[1], ww[4], S1);
    S1 = fma2(P2[1], ww[7], S1);
    S1 = fma2(P0[2], ww[2], S1);
    S1 = fma2(P1[2], ww[5], S1);
    S1 = fma2(P2[2], ww[8], S1);
    // j = 2
    S2 = mul2(P0[1], ww[0]);
    S2 = fma2(P1[1], ww[3], S2);
    S2 = fma2(P2[1], ww[6], S2);
    S2 = fma2(P0[2], ww[1], S2);
    S2 = fma2(P1[2], ww[4], S2);
    S2 = fma2(P2[2], ww[7], S2);
    S2 = fma2(P0[3], ww[2], S2);
    S2 = fma2(P1[3], ww[5], S2);
    S2 = fma2(P2[3], ww[8], S2);
    // j = 3
    S3 = mul2(P0[2], ww[0]);
    S3 = fma2(P1[2], ww[3], S3);
    S3 = fma2(P2[2], ww[6], S3);
    S3 = fma2(P0[3], ww[1], S3);
    S3 = fma2(P1[3], ww[4], S3);
    S3 = fma2(P2[3], ww[7], S3);

    float o0[4], o1[4];
    upk2(S0, o0[0], o1[0]);
    upk2(S1, o0[1], o1[1]);
    upk2(S2, o0[2], o1[2]);
    upk2(S3, o0[3], o1[3]);

    // Submanifold mask: write only at active (nonzero-input) sites.
#pragma unroll
    for (int j = 0; j < 4; j++) {
        o0[j] = (rm[j] != 0.0f) ? o0[j] : 0.0f;
        o1[j] = (rn[j] != 0.0f) ? o1[j] : 0.0f;
    }

    // Default (evict-normal) stores: let dirty output lines linger in L2.
    float4* yout = y + 2 * (size_t)gid;
    yout[0] = make_float4(o0[0], o0[1], o0[2], o0[3]);
    yout[1] = make_float4(o1[0], o1[1], o1[2], o1[3]);
}

extern "C" void kernel_launch(void* const* d_in, const int* in_sizes, int n_in,
                              void* d_out, int out_size)
{
    const float4* x = (const float4*)d_in[0];
    const float* W = (const float*)d_in[1];
    float4* y = (float4*)d_out;

    int n_pairs = in_sizes[0] / 8;     // one thread per 8 floats (2 rows)
    int threads = 256;
    int blocks = (n_pairs + threads - 1) / threads;
    subm_conv_pair_f32x2_kernel<<<blocks, threads>>>(x, W, y, n_pairs);
}

// round 10
// speedup vs baseline: 1.0390x; 1.0007x over previous
#include <cuda_runtime.h>
#include <cstdint>

// Submanifold 3x3 conv (cross-correlation, SAME) on independent 4x4x1 tiles.
// One thread per ROW-PAIR (32B); tile = 2 adjacent lanes. Single butterfly
// exchange (shfl.xor 1) supplies the one partner row each lane needs. Both
// output rows computed together with packed fma.rn.f32x2.
// NEW: 256-bit global load/store (sm_100+): one LDG.256 + one STG.256 per
// thread instead of 2+2 128-bit ops — fewer L1tex wavefronts, fewer instrs.

__device__ __forceinline__ unsigned long long pk2(float lo, float hi) {
    unsigned long long r;
    asm("mov.b64 %0, {%1, %2};" : "=l"(r) : "f"(lo), "f"(hi));
    return r;
}
__device__ __forceinline__ unsigned long long fma2(
    unsigned long long a, unsigned long long b, unsigned long long c) {
    unsigned long long d;
    asm("fma.rn.f32x2 %0, %1, %2, %3;" : "=l"(d) : "l"(a), "l"(b), "l"(c));
    return d;
}
__device__ __forceinline__ unsigned long long mul2(
    unsigned long long a, unsigned long long b) {
    unsigned long long d;
    asm("mul.rn.f32x2 %0, %1, %2;" : "=l"(d) : "l"(a), "l"(b));
    return d;
}
__device__ __forceinline__ void upk2(unsigned long long v, float& lo, float& hi) {
    asm("mov.b64 {%0, %1}, %2;" : "=f"(lo), "=f"(hi) : "l"(v));
}

__global__ __launch_bounds__(256) void subm_conv_pair_v8_kernel(
    const float* __restrict__ x,
    const float* __restrict__ W,
    float* __restrict__ y,
    int n_pairs)
{
    int gid = blockIdx.x * blockDim.x + threadIdx.x;
    if (gid >= n_pairs) return;

    // One 256-bit streaming load: my two tile rows (8 floats, 32B-aligned).
    const float* xin = x + 8 * (size_t)gid;
    float rm[4], rn[4];
    asm("ld.global.cs.v8.f32 {%0,%1,%2,%3,%4,%5,%6,%7}, [%8];"
        : "=f"(rm[0]), "=f"(rm[1]), "=f"(rm[2]), "=f"(rm[3]),
          "=f"(rn[0]), "=f"(rn[1]), "=f"(rn[2]), "=f"(rn[3])
        : "l"(xin));

    bool top = ((gid & 1) == 0);

    // Broadcast weight loads (uniform address -> L1 broadcast hits).
    float4 w03 = __ldg(reinterpret_cast<const float4*>(W));
    float4 w47 = __ldg(reinterpret_cast<const float4*>(W) + 1);
    float  w8f = __ldg(W + 8);

    // Butterfly exchange with partner lane (same tile): send the row my
    // partner needs (top lane sends its lower row rn; bottom sends rm).
    float s0 = top ? rn[0] : rm[0];
    float s1 = top ? rn[1] : rm[1];
    float s2 = top ? rn[2] : rm[2];
    float s3 = top ? rn[3] : rm[3];
    float v0 = __shfl_xor_sync(0xffffffffu, s0, 1);
    float v1 = __shfl_xor_sync(0xffffffffu, s1, 1);
    float v2 = __shfl_xor_sync(0xffffffffu, s2, 1);
    float v3 = __shfl_xor_sync(0xffffffffu, s3, 1);

    // a = row above rm (zero at tile top); b = row below rn (zero at bottom).
    float ra[4], rb[4];
    ra[0] = top ? 0.0f : v0;  rb[0] = top ? v0 : 0.0f;
    ra[1] = top ? 0.0f : v1;  rb[1] = top ? v1 : 0.0f;
    ra[2] = top ? 0.0f : v2;  rb[2] = top ? v2 : 0.0f;
    ra[3] = top ? 0.0f : v3;  rb[3] = top ? v3 : 0.0f;

    // Packed input rows: lo half -> output row rm (inputs ra,rm,rn),
    // hi half -> output row rn (inputs rm,rn,rb).
    unsigned long long P0[4], P1[4], P2[4];
#pragma unroll
    for (int c = 0; c < 4; c++) {
        P0[c] = pk2(ra[c], rm[c]);
        P1[c] = pk2(rm[c], rn[c]);
        P2[c] = pk2(rn[c], rb[c]);
    }

    unsigned long long ww[9];
    ww[0] = pk2(w03.x, w03.x);
    ww[1] = pk2(w03.y, w03.y);
    ww[2] = pk2(w03.z, w03.z);
    ww[3] = pk2(w03.w, w03.w);
    ww[4] = pk2(w47.x, w47.x);
    ww[5] = pk2(w47.y, w47.y);
    ww[6] = pk2(w47.z, w47.z);
    ww[7] = pk2(w47.w, w47.w);
    ww[8] = pk2(w8f,  w8f);

    // S[j] = sum over weight rows k, cols c of Pk[j+c-1]*w[k][c]; taps with
    // j+c-1 outside [0,3] are zero (dropped).
    unsigned long long S0, S1, S2, S3;
    // j = 0
    S0 = mul2(P0[0], ww[1]);
    S0 = fma2(P1[0], ww[4], S0);
    S0 = fma2(P2[0], ww[7], S0);
    S0 = fma2(P0[1], ww[2], S0);
    S0 = fma2(P1[1], ww[5], S0);
    S0 = fma2(P2[1], ww[8], S0);
    // j = 1
    S1 = mul2(P0[0], ww[0]);
    S1 = fma2(P1[0], ww[3], S1);
    S1 = fma2(P2[0], ww[6], S1);
    S1 = fma2(P0[1], ww[1], S1);
    S1 = fma2(P1[1], ww[4], S1);
    S1 = fma2(P2[1], ww[7], S1);
    S1 = fma2(P0[2], ww[2], S1);
    S1 = fma2(P1[2], ww[5], S1);
    S1 = fma2(P2[2], ww[8], S1);
    // j = 2
    S2 = mul2(P0[1], ww[0]);
    S2 = fma2(P1[1], ww[3], S2);
    S2 = fma2(P2[1], ww[6], S2);
    S2 = fma2(P0[2], ww[1], S2);
    S2 = fma2(P1[2], ww[4], S2);
    S2 = fma2(P2[2], ww[7], S2);
    S2 = fma2(P0[3], ww[2], S2);
    S2 = fma2(P1[3], ww[5], S2);
    S2 = fma2(P2[3], ww[8], S2);
    // j = 3
    S3 = mul2(P0[2], ww[0]);
    S3 = fma2(P1[2], ww[3], S3);
    S3 = fma2(P2[2], ww[6], S3);
    S3 = fma2(P0[3], ww[1], S3);
    S3 = fma2(P1[3], ww[4], S3);
    S3 = fma2(P2[3], ww[7], S3);

    float o0[4], o1[4];
    upk2(S0, o0[0], o1[0]);
    upk2(S1, o0[1], o1[1]);
    upk2(S2, o0[2], o1[2]);
    upk2(S3, o0[3], o1[3]);

    // Submanifold mask: write only at active (nonzero-input) sites.
#pragma unroll
    for (int j = 0; j < 4; j++) {
        o0[j] = (rm[j] != 0.0f) ? o0[j] : 0.0f;
        o1[j] = (rn[j] != 0.0f) ? o1[j] : 0.0f;
    }

    // One 256-bit store: both output rows.
    float* yout = y + 8 * (size_t)gid;
    asm volatile("st.global.v8.f32 [%0], {%1,%2,%3,%4,%5,%6,%7,%8};"
        :: "l"(yout),
           "f"(o0[0]), "f"(o0[1]), "f"(o0[2]), "f"(o0[3]),
           "f"(o1[0]), "f"(o1[1]), "f"(o1[2]), "f"(o1[3])
        : "memory");
}

extern "C" void kernel_launch(void* const* d_in, const int* in_sizes, int n_in,
                              void* d_out, int out_size)
{
    const float* x = (const float*)d_in[0];
    const float* W = (const float*)d_in[1];
    float* y = (float*)d_out;

    int n_pairs = in_sizes[0] / 8;     // one thread per 8 floats (2 rows)
    int threads = 256;
    int blocks = (n_pairs + threads - 1) / threads;
    subm_conv_pair_v8_kernel<<<blocks, threads>>>(x, W, y, n_pairs);
}